// round 7
// baseline (speedup 1.0000x reference)
#include <cuda_runtime.h>
#include <math.h>
#include <stdint.h>

// ============================================================================
// ClassificationLoss OHEM: B=16, N=1M anchors/image. Exact value-at-rank via
// 16-bit packed histograms (smem AND gmem), slot gather without pos re-read
// (positive exclusion lists), O(n) sub-histogram selection.
// ============================================================================

#define BB 16
#define NN (1 << 20)
#define NB 8192                 // fine bins
#define NBH (NB / 2)            // packed 32-bit words (16KB smem)
#define NBC 128                 // coarse bins
#define FPC (NB / NBC)          // 64
#define NU (NN - 512)
#define NUV (NU / 4)            // 262016 float4s
#define NCHUNK 64
#define CHUNK (NN / NCHUNK)     // 16384 elems per block
#define VITERS (CHUNK / 4 / 512)// 8
#define CAP_CAND 8192
#define T0 0.002f
#define MAXQ 1024
#define SLOTS 1152
#define SLOTC 256
#define POSCAP 32768
#define EXC 32

// -------- scratch (static device globals) ----------------------------------
__device__ unsigned int   g_h16[BB][NBH];                // packed 16-bit hist
__device__ int            g_slotid[BB][NB];
__device__ unsigned short g_slotid16[BB][NB];
__device__ float          g_slotbuf[BB][SLOTS][SLOTC];   // 18.9 MB
__device__ int            g_slotcnt[BB][SLOTS];
__device__ int            g_nslots[BB];
__device__ int            g_numpos[BB];
__device__ float          g_acc_ph[BB];
__device__ float          g_acc_r[BB];
__device__ float          g_cand_u[BB][CAP_CAND];
__device__ int            g_cand_j[BB][CAP_CAND];
__device__ int            g_candcnt[BB];
__device__ int            g_qrank[BB][MAXQ];
__device__ int            g_qbin[BB][MAXQ];
__device__ int            g_qt[BB][MAXQ];
__device__ int            g_qcnt[BB];
__device__ float          g_posv[BB][POSCAP];            // positive conf values
__device__ int            g_poscnt[BB];
__device__ float          g_exv[BB][SLOTS][EXC];         // per-slot exclusions
__device__ int            g_excnt[BB][SLOTS];

__device__ __forceinline__ float log_c(float x) {
    return fmaxf(logf(x), -100.0f);
}
__device__ __forceinline__ int conf_bin(float v) {
    int b = (int)(v * (float)NB);
    return b < 0 ? 0 : (b >= NB ? NB - 1 : b);
}
__device__ __forceinline__ int sub_idx(float v, int bin) {
    float frac = v * (float)NB - (float)bin;
    int s = (int)(frac * 256.0f);
    return s < 0 ? 0 : (s > 255 ? 255 : s);
}
__device__ __forceinline__ int hist_at(int b, int fb) {
    unsigned int w = g_h16[b][fb >> 1];
    return (fb & 1) ? (int)(w >> 16) : (int)(w & 0xFFFFu);
}

// ---------------------------------------------------------------------------
__global__ void k_init() {
    int tid = blockIdx.x * blockDim.x + threadIdx.x;   // 131072 threads
    if (tid < BB * NBH) ((unsigned int*)g_h16)[tid] = 0u;
    if (tid < BB * NB) {
        int b = tid >> 13, bin = tid & (NB - 1);
        g_slotid[b][bin] = -1;
        g_slotid16[b][bin] = 0xFFFFu;
    }
    if (tid < BB * SLOTS) {
        g_slotcnt[tid / SLOTS][tid % SLOTS] = 0;
        g_excnt[tid / SLOTS][tid % SLOTS] = 0;
    }
    if (tid < BB) {
        g_nslots[tid] = 0;
        g_numpos[tid] = 0;
        g_acc_ph[tid] = 0.0f;
        g_acc_r[tid]  = 0.0f;
        g_candcnt[tid] = 0;
        g_poscnt[tid] = 0;
    }
}

// ---------------------------------------------------------------------------
// Fused pass 1: unconditional packed smem histogram (positives compensated),
// pos count/loss/value-list, rand_u candidates.
__global__ void __launch_bounds__(512) k_main(const uint4* __restrict__ pos,
                                              const float4* __restrict__ conf,
                                              const float4* __restrict__ u) {
    __shared__ unsigned int sh[NBH];             // 16 KB
    int b = blockIdx.y;
    int chunk = blockIdx.x;
    int tid = threadIdx.x;

    for (int j = tid; j < NBH; j += 512) sh[j] = 0u;
    __syncthreads();

    const uint4*  P = pos  + ((size_t)b * NN + (size_t)chunk * CHUNK) / 4;
    const float4* C = conf + ((size_t)b * NN + (size_t)chunk * CHUNK) / 4;
    float ploss = 0.0f;
    int   pcnt  = 0;
#pragma unroll 2
    for (int it = 0; it < VITERS; it++) {
        int i = it * 512 + tid;
        uint4  p = __ldcs(P + i);
        float4 v = __ldcs(C + i);
        {
            int bn = conf_bin(v.x);
            atomicAdd(&sh[bn >> 1], 1u << ((bn & 1) * 16));
            if (p.x) { pcnt++; ploss -= log_c(v.x);
                       atomicAdd(&sh[bn >> 1], (unsigned)(-(1u << ((bn & 1) * 16))));
                       int ip = atomicAdd(&g_poscnt[b], 1); if (ip < POSCAP) g_posv[b][ip] = v.x; }
        }
        {
            int bn = conf_bin(v.y);
            atomicAdd(&sh[bn >> 1], 1u << ((bn & 1) * 16));
            if (p.y) { pcnt++; ploss -= log_c(v.y);
                       atomicAdd(&sh[bn >> 1], (unsigned)(-(1u << ((bn & 1) * 16))));
                       int ip = atomicAdd(&g_poscnt[b], 1); if (ip < POSCAP) g_posv[b][ip] = v.y; }
        }
        {
            int bn = conf_bin(v.z);
            atomicAdd(&sh[bn >> 1], 1u << ((bn & 1) * 16));
            if (p.z) { pcnt++; ploss -= log_c(v.z);
                       atomicAdd(&sh[bn >> 1], (unsigned)(-(1u << ((bn & 1) * 16))));
                       int ip = atomicAdd(&g_poscnt[b], 1); if (ip < POSCAP) g_posv[b][ip] = v.z; }
        }
        {
            int bn = conf_bin(v.w);
            atomicAdd(&sh[bn >> 1], 1u << ((bn & 1) * 16));
            if (p.w) { pcnt++; ploss -= log_c(v.w);
                       atomicAdd(&sh[bn >> 1], (unsigned)(-(1u << ((bn & 1) * 16))));
                       int ip = atomicAdd(&g_poscnt[b], 1); if (ip < POSCAP) g_posv[b][ip] = v.w; }
        }
    }

    // rand_u candidates (validity filtered later)
    const float4* U = u + (size_t)b * NUV;
    for (int vi = chunk * 512 + tid; vi < NUV; vi += NCHUNK * 512) {
        float4 uu = __ldcs(U + vi);
        int j4 = vi * 4;
        if (uu.x < T0) { int p = atomicAdd(&g_candcnt[b], 1); if (p < CAP_CAND) { g_cand_u[b][p] = uu.x; g_cand_j[b][p] = j4;     } }
        if (uu.y < T0) { int p = atomicAdd(&g_candcnt[b], 1); if (p < CAP_CAND) { g_cand_u[b][p] = uu.y; g_cand_j[b][p] = j4 + 1; } }
        if (uu.z < T0) { int p = atomicAdd(&g_candcnt[b], 1); if (p < CAP_CAND) { g_cand_u[b][p] = uu.z; g_cand_j[b][p] = j4 + 2; } }
        if (uu.w < T0) { int p = atomicAdd(&g_candcnt[b], 1); if (p < CAP_CAND) { g_cand_u[b][p] = uu.w; g_cand_j[b][p] = j4 + 3; } }
    }

    for (int o = 16; o; o >>= 1) {
        ploss += __shfl_down_sync(0xffffffffu, ploss, o);
        pcnt  += __shfl_down_sync(0xffffffffu, pcnt, o);
    }
    if ((tid & 31) == 0) {
        if (ploss != 0.0f) atomicAdd(&g_acc_ph[b], ploss);
        if (pcnt) atomicAdd(&g_numpos[b], pcnt);
    }

    __syncthreads();
    for (int j = tid; j < NBH; j += 512) {
        unsigned int w = sh[j];
        if (w) atomicAdd(&g_h16[b][j], w);      // one atomic per bin PAIR
    }
}

// ---------------------------------------------------------------------------
// Per image: coarse sums + top-512-smallest-u + rank->bin + slot table +
// positive exclusion routing.
__global__ void __launch_bounds__(1024) k_mid() {
    int b = blockIdx.x;
    int tid = threadIdx.x;
    __shared__ int   scoarse[NBC];
    __shared__ float su[1024];
    __shared__ int   sj[1024];

    if (tid < NBC) {
        int s = 0;
        int base = tid * (FPC / 2);              // word base for this coarse bin
#pragma unroll 8
        for (int f = 0; f < FPC / 2; f++) {
            unsigned int w = g_h16[b][base + f];
            s += (int)(w & 0xFFFFu) + (int)(w >> 16);
        }
        scoarse[tid] = s;
    }
    if (tid == 0) g_qcnt[b] = 512;
    if (tid < 512) g_qrank[b][tid] = tid;
    __syncthreads();

    int num_neg = NN - g_numpos[b];
    int limit = num_neg - 512;
    int K = min(g_candcnt[b], CAP_CAND);
    int iters = (K + 1023) / 1024;
    for (int it = 0; it < iters; it++) {
        int i = it * 1024 + tid;
        bool active = (i < K);
        float ui = 1.0e30f; int ji = 0x7fffffff;
        if (active) {
            ji = g_cand_j[b][i];
            ui = (ji < limit) ? g_cand_u[b][i] : 1.0e30f;
        }
        bool valid = active && (ji < limit);
        int rank = 0;
        for (int base = 0; base < K; base += 1024) {
            __syncthreads();
            int k = base + tid;
            if (k < K) {
                int jk = g_cand_j[b][k];
                sj[tid] = jk;
                su[tid] = (jk < limit) ? g_cand_u[b][k] : 1.0e30f;
            }
            __syncthreads();
            int lim = min(1024, K - base);
            for (int kk = 0; kk < lim; kk++) {
                float uk = su[kk];
                int   jk = sj[kk];
                rank += (uk < ui) || (uk == ui && jk < ji);
            }
        }
        if (valid && rank < 512) {
            int q = atomicAdd(&g_qcnt[b], 1);
            if (q < MAXQ) g_qrank[b][q] = 512 + ji;
        }
    }
    __syncthreads();

    int qn = min(g_qcnt[b], MAXQ);
    for (int q = tid; q < qn; q += 1024) {
        int R = g_qrank[b][q];
        if (R >= num_neg) { g_qbin[b][q] = -1; continue; }
        int rem = R;
        int cb = NBC - 1;
        for (; cb >= 0; cb--) {
            int c = scoarse[cb];
            if (rem < c) break;
            rem -= c;
        }
        int bin = -1;
        if (cb >= 0) {
            for (int f = FPC - 1; f >= 0; f--) {
                int fb = cb * FPC + f;
                int h = hist_at(b, fb);
                if (rem < h) { bin = fb; break; }
                rem -= h;
            }
        }
        g_qbin[b][q] = bin;
        g_qt[b][q] = rem;
        if (bin >= 0 && g_slotid[b][bin] == -1) {
            int ns = atomicAdd(&g_nslots[b], 1);
            if (atomicCAS(&g_slotid[b][bin], -1, ns) == -1)
                g_slotid16[b][bin] = (unsigned short)ns;
        }
    }
    __syncthreads();

    // route positives landing in interesting bins to per-slot exclusion lists
    int pc = min(g_poscnt[b], POSCAP);
    for (int ip = tid; ip < pc; ip += 1024) {
        float v = g_posv[b][ip];
        int s = g_slotid[b][conf_bin(v)];
        if (s >= 0) {
            int e = atomicAdd(&g_excnt[b][s], 1);
            if (e < EXC) g_exv[b][s][e] = v;
        }
    }
}

// ---------------------------------------------------------------------------
// Pass 2: gather ALL elements (pos excluded later) in interesting bins.
__global__ void __launch_bounds__(512) k_gather(const float4* __restrict__ conf) {
    __shared__ unsigned short sid[NB];         // 16 KB
    int b = blockIdx.y;
    int chunk = blockIdx.x;
    int tid = threadIdx.x;
    const unsigned int* srcp = (const unsigned int*)g_slotid16[b];
    unsigned int* dstp = (unsigned int*)sid;
    for (int j = tid; j < NB / 2; j += 512) dstp[j] = srcp[j];
    __syncthreads();

    const float4* C = conf + ((size_t)b * NN + (size_t)chunk * CHUNK) / 4;
#pragma unroll 2
    for (int it = 0; it < VITERS; it += 2) {
        int i0 = it * 512 + tid;
        int i1 = (it + 1) * 512 + tid;
        float4 v0 = __ldcs(C + i0);
        float4 v1 = __ldcs(C + i1);
        unsigned short s;
        if ((s = sid[conf_bin(v0.x)]) != 0xFFFFu) { int w = atomicAdd(&g_slotcnt[b][s], 1); if (w < SLOTC) g_slotbuf[b][s][w] = v0.x; }
        if ((s = sid[conf_bin(v0.y)]) != 0xFFFFu) { int w = atomicAdd(&g_slotcnt[b][s], 1); if (w < SLOTC) g_slotbuf[b][s][w] = v0.y; }
        if ((s = sid[conf_bin(v0.z)]) != 0xFFFFu) { int w = atomicAdd(&g_slotcnt[b][s], 1); if (w < SLOTC) g_slotbuf[b][s][w] = v0.z; }
        if ((s = sid[conf_bin(v0.w)]) != 0xFFFFu) { int w = atomicAdd(&g_slotcnt[b][s], 1); if (w < SLOTC) g_slotbuf[b][s][w] = v0.w; }
        if ((s = sid[conf_bin(v1.x)]) != 0xFFFFu) { int w = atomicAdd(&g_slotcnt[b][s], 1); if (w < SLOTC) g_slotbuf[b][s][w] = v1.x; }
        if ((s = sid[conf_bin(v1.y)]) != 0xFFFFu) { int w = atomicAdd(&g_slotcnt[b][s], 1); if (w < SLOTC) g_slotbuf[b][s][w] = v1.y; }
        if ((s = sid[conf_bin(v1.z)]) != 0xFFFFu) { int w = atomicAdd(&g_slotcnt[b][s], 1); if (w < SLOTC) g_slotbuf[b][s][w] = v1.z; }
        if ((s = sid[conf_bin(v1.w)]) != 0xFFFFu) { int w = atomicAdd(&g_slotcnt[b][s], 1); if (w < SLOTC) g_slotbuf[b][s][w] = v1.w; }
    }
}

// ---------------------------------------------------------------------------
// One warp per query: t-th largest among NEGATIVES in the gathered bin =
// multiset (slot values) minus (exclusion values).
__global__ void __launch_bounds__(256) k_resolve() {
    __shared__ float vals[8][SLOTC];           // 8 KB
    __shared__ int   subh[8][256];             // 8 KB
    __shared__ float mval[8][32];
    __shared__ float exsel[8][32];
    __shared__ int   mcnt[8];
    __shared__ int   ecnt[8];

    int b = blockIdx.y;
    int w = threadIdx.x >> 5, lane = threadIdx.x & 31;
    int q = blockIdx.x * 8 + w;                // 128 * 8 = 1024 = MAXQ
    int qn = min(g_qcnt[b], MAXQ);
    if (q >= qn) return;
    int bin = g_qbin[b][q];
    if (bin < 0) return;
    int s = g_slotid[b][bin];
    if (s < 0) return;
    int n = min(g_slotcnt[b][s], SLOTC);
    int m_ex = min(g_excnt[b][s], EXC);
    int t = g_qt[b][q];

    for (int i = lane; i < n; i += 32) vals[w][i] = g_slotbuf[b][s][i];
    for (int k = lane; k < 256; k += 32) subh[w][k] = 0;
    if (lane == 0) { mcnt[w] = 0; ecnt[w] = 0; }
    __syncwarp();
    for (int i = lane; i < n; i += 32) atomicAdd(&subh[w][sub_idx(vals[w][i], bin)], 1);
    // subtract positives assigned to this slot
    for (int i = lane; i < m_ex; i += 32) atomicSub(&subh[w][sub_idx(g_exv[b][s][i], bin)], 1);
    __syncwarp();

    // lane L owns sub-bins [L*8, L*8+8); larger sub == larger value
    int h[8], lt = 0;
#pragma unroll
    for (int k = 0; k < 8; k++) { h[k] = subh[w][lane * 8 + k]; lt += h[k]; }
    int s1 = lt;
#pragma unroll
    for (int o = 1; o < 32; o <<= 1) {
        int t2 = __shfl_down_sync(0xffffffffu, s1, o);
        if (lane + o < 32) s1 += t2;
    }
    int cum = s1 - lt;                          // negatives strictly above this lane's range
    int found = -1, tp_local = 0;
#pragma unroll
    for (int k = 7; k >= 0; k--) {
        int hh = h[k];
        if (found < 0 && t >= cum && t < cum + hh) { found = lane * 8 + k; tp_local = t - cum; }
        cum += hh;
    }
    unsigned bal = __ballot_sync(0xffffffffu, found >= 0);
    if (!bal) return;
    int src = __ffs(bal) - 1;
    int sel_sub = __shfl_sync(0xffffffffu, found, src);
    int tp = __shfl_sync(0xffffffffu, tp_local, src);

    for (int i = lane; i < n; i += 32) {
        float x = vals[w][i];
        if (sub_idx(x, bin) == sel_sub) {
            int p = atomicAdd(&mcnt[w], 1);
            if (p < 32) mval[w][p] = x;
        }
    }
    for (int i = lane; i < m_ex; i += 32) {
        float x = g_exv[b][s][i];
        if (sub_idx(x, bin) == sel_sub) {
            int p = atomicAdd(&ecnt[w], 1);
            if (p < 32) exsel[w][p] = x;
        }
    }
    __syncwarp();
    if (lane == 0) {
        int m  = min(mcnt[w], 32);
        int me = min(ecnt[w], 32);
        float res = 0.5f;
        for (int a = 0; a < m; a++) {
            float x = mval[w][a];
            int gt_a = 0, eq_a = 0, gt_e = 0, eq_e = 0;
            for (int c = 0; c < m; c++) {
                float y = mval[w][c];
                gt_a += (y > x);
                eq_a += (y == x);
            }
            for (int c = 0; c < me; c++) {
                float y = exsel[w][c];
                gt_e += (y > x);
                eq_e += (y == x);
            }
            int gtn = gt_a - gt_e, eqn = eq_a - eq_e;
            if (eqn > 0 && gtn <= tp && tp < gtn + eqn) { res = x; break; }
        }
        float term = -log_c(1.0f - res);
        if (q < 512) atomicAdd(&g_acc_ph[b], term);
        else         atomicAdd(&g_acc_r[b],  term);
    }
}

// ---------------------------------------------------------------------------
__global__ void k_final(float* __restrict__ out) {
    int b = threadIdx.x;
    if (b < BB) {
        int np = g_numpos[b];
        int nn = NN - np;
        bool has_rem = (nn - 512) > 0;
        float sn = (float)(np + min(512, nn));
        out[b] = has_rem ? (g_acc_ph[b] + g_acc_r[b])
                         : (g_acc_ph[b] / fmaxf(sn, 1.0f));
    }
}

// ===========================================================================
extern "C" void kernel_launch(void* const* d_in, const int* in_sizes, int n_in,
                              void* d_out, int out_size) {
    (void)in_sizes; (void)n_in; (void)out_size;
    const uint4*  pos  = (const uint4*)d_in[0];
    const float4* conf = (const float4*)d_in[1];
    const float4* u    = (const float4*)d_in[2];
    float*        out  = (float*)d_out;

    k_init<<<256, 512>>>();                        // 131072 threads
    k_main<<<dim3(NCHUNK, BB), 512>>>(pos, conf, u);
    k_mid<<<BB, 1024>>>();
    k_gather<<<dim3(NCHUNK, BB), 512>>>(conf);
    k_resolve<<<dim3(128, BB), 256>>>();
    k_final<<<1, 32>>>(out);
}